// round 1
// baseline (speedup 1.0000x reference)
#include <cuda_runtime.h>
#include <cuda_bf16.h>
#include <mma.h>

using namespace nvcuda;

// Problem constants
#define BB 16
#define NN 1024
#define DD 768
#define HH 12
#define HD 64
#define MTOT (BB * NN)   // 16384
#define SCALE 0.125f     // HD^-0.5

// Scratch (allocation-free rule: __device__ globals)
__device__ float g_Q[MTOT * DD];
__device__ float g_K[MTOT * DD];
__device__ float g_AO[MTOT * DD];

// ---------------------------------------------------------------------------
// Generic GEMM: C[m,n] = sum_k A[m,k] * W[n,k] + bias[n]
// Tiles: 64x64 per block, BK=32, 4 warps each computing 32x32 (2x2 wmma tf32).
// ---------------------------------------------------------------------------
#define GLD 48   // BK(32) + 16 pad: keeps every fragment pointer 32B-aligned
#define CLD 72

__global__ __launch_bounds__(128) void gemm_bias_kernel(
    const float* __restrict__ A, const float* __restrict__ W,
    const float* __restrict__ bias, float* __restrict__ C,
    int M, int Nn, int Kk)
{
    __shared__ float As[64 * GLD];
    __shared__ float Bs[64 * GLD];
    __shared__ float Cs[64 * CLD];

    const int bm = blockIdx.y * 64;
    const int bn = blockIdx.x * 64;
    const int tid = threadIdx.x;
    const int warp = tid >> 5;
    const int wy = warp >> 1;   // 0..1 (M dir)
    const int wx = warp & 1;    // 0..1 (N dir)

    wmma::fragment<wmma::accumulator, 16, 16, 8, float> acc[2][2];
#pragma unroll
    for (int i = 0; i < 2; i++)
#pragma unroll
        for (int j = 0; j < 2; j++)
            wmma::fill_fragment(acc[i][j], 0.0f);

    for (int k0 = 0; k0 < Kk; k0 += 32) {
        // Stage A tile (64x32) and W tile (64x32), float4 coalesced.
#pragma unroll
        for (int l = 0; l < 4; l++) {
            int idx = tid + l * 128;          // 0..511
            int r = idx >> 3;                 // 0..63
            int j = (idx & 7) * 4;            // 0..28
            *(float4*)&As[r * GLD + j] =
                *(const float4*)&A[(bm + r) * Kk + k0 + j];
            *(float4*)&Bs[r * GLD + j] =
                *(const float4*)&W[(bn + r) * Kk + k0 + j];
        }
        __syncthreads();

#pragma unroll
        for (int kk = 0; kk < 32; kk += 8) {
            wmma::fragment<wmma::matrix_a, 16, 16, 8, wmma::precision::tf32,
                           wmma::row_major> fa[2];
            wmma::fragment<wmma::matrix_b, 16, 16, 8, wmma::precision::tf32,
                           wmma::col_major> fb[2];
#pragma unroll
            for (int i = 0; i < 2; i++) {
                wmma::load_matrix_sync(fa[i], &As[(wy * 32 + i * 16) * GLD + kk], GLD);
#pragma unroll
                for (int t = 0; t < fa[i].num_elements; t++)
                    fa[i].x[t] = wmma::__float_to_tf32(fa[i].x[t]);
            }
#pragma unroll
            for (int j = 0; j < 2; j++) {
                wmma::load_matrix_sync(fb[j], &Bs[(wx * 32 + j * 16) * GLD + kk], GLD);
#pragma unroll
                for (int t = 0; t < fb[j].num_elements; t++)
                    fb[j].x[t] = wmma::__float_to_tf32(fb[j].x[t]);
            }
#pragma unroll
            for (int i = 0; i < 2; i++)
#pragma unroll
                for (int j = 0; j < 2; j++)
                    wmma::mma_sync(acc[i][j], fa[i], fb[j], acc[i][j]);
        }
        __syncthreads();
    }

    // Epilogue: stage to smem, add bias, vectorized store.
#pragma unroll
    for (int i = 0; i < 2; i++)
#pragma unroll
        for (int j = 0; j < 2; j++)
            wmma::store_matrix_sync(
                &Cs[(wy * 32 + i * 16) * CLD + wx * 32 + j * 16],
                acc[i][j], CLD, wmma::mem_row_major);
    __syncthreads();

#pragma unroll
    for (int l = 0; l < 8; l++) {
        int idx = tid + l * 128;    // 0..1023
        int r = idx >> 4;           // 0..63
        int j = (idx & 15) * 4;     // 0..60
        float4 v = *(float4*)&Cs[r * CLD + j];
        float4 bv = *(const float4*)&bias[bn + j];
        v.x += bv.x; v.y += bv.y; v.z += bv.z; v.w += bv.w;
        *(float4*)&C[(bm + r) * Nn + bn + j] = v;
    }
}

// ---------------------------------------------------------------------------
// Flash attention, V = K. One block = one (b,h) and a 64-query tile.
// Online softmax state in smem; wmma tf32 for S = Q*K^T and O += P*V.
// ---------------------------------------------------------------------------
#define ALD 72
#define ATT_SMEM ((4 * 64 * ALD + 128) * 4)   // 74240 bytes

__global__ __launch_bounds__(128) void attn_kernel(
    const float* __restrict__ Q, const float* __restrict__ K,
    float* __restrict__ O)
{
    extern __shared__ float sm[];
    float* Qs   = sm;
    float* Ks   = sm + 64 * ALD;
    float* Ss   = sm + 2 * 64 * ALD;
    float* Os   = sm + 3 * 64 * ALD;
    float* rmax = sm + 4 * 64 * ALD;
    float* rsum = rmax + 64;

    const int b  = blockIdx.z;
    const int h  = blockIdx.y;
    const int q0 = blockIdx.x * 64;
    const int tid = threadIdx.x;
    const int warp = tid >> 5;
    const int lane = tid & 31;
    const int wy = warp >> 1;
    const int wx = warp & 1;

    // Load Q tile, pre-scaled by SCALE.
    const float* qbase = Q + ((b * NN + q0) * DD + h * HD);
#pragma unroll
    for (int l = 0; l < 8; l++) {
        int idx = tid + l * 128;
        int r = idx >> 4;
        int j = (idx & 15) * 4;
        float4 v = *(const float4*)&qbase[r * DD + j];
        v.x *= SCALE; v.y *= SCALE; v.z *= SCALE; v.w *= SCALE;
        *(float4*)&Qs[r * ALD + j] = v;
    }
    for (int idx = tid; idx < 64 * ALD; idx += 128) Os[idx] = 0.0f;
    if (tid < 64) { rmax[tid] = -INFINITY; rsum[tid] = 0.0f; }
    __syncthreads();

    for (int kt = 0; kt < NN / 64; kt++) {
        // Stage K tile (also V tile).
        const float* kbase = K + ((b * NN + kt * 64) * DD + h * HD);
#pragma unroll
        for (int l = 0; l < 8; l++) {
            int idx = tid + l * 128;
            int r = idx >> 4;
            int j = (idx & 15) * 4;
            *(float4*)&Ks[r * ALD + j] = *(const float4*)&kbase[r * DD + j];
        }
        __syncthreads();

        // S = Qs * Ks^T (64x64, K-dim = HD = 64)
        wmma::fragment<wmma::accumulator, 16, 16, 8, float> sacc[2][2];
#pragma unroll
        for (int i = 0; i < 2; i++)
#pragma unroll
            for (int j = 0; j < 2; j++)
                wmma::fill_fragment(sacc[i][j], 0.0f);

#pragma unroll
        for (int kk = 0; kk < HD; kk += 8) {
            wmma::fragment<wmma::matrix_a, 16, 16, 8, wmma::precision::tf32,
                           wmma::row_major> fa[2];
            wmma::fragment<wmma::matrix_b, 16, 16, 8, wmma::precision::tf32,
                           wmma::col_major> fb[2];
#pragma unroll
            for (int i = 0; i < 2; i++) {
                wmma::load_matrix_sync(fa[i], &Qs[(wy * 32 + i * 16) * ALD + kk], ALD);
#pragma unroll
                for (int t = 0; t < fa[i].num_elements; t++)
                    fa[i].x[t] = wmma::__float_to_tf32(fa[i].x[t]);
            }
#pragma unroll
            for (int j = 0; j < 2; j++) {
                wmma::load_matrix_sync(fb[j], &Ks[(wx * 32 + j * 16) * ALD + kk], ALD);
#pragma unroll
                for (int t = 0; t < fb[j].num_elements; t++)
                    fb[j].x[t] = wmma::__float_to_tf32(fb[j].x[t]);
            }
#pragma unroll
            for (int i = 0; i < 2; i++)
#pragma unroll
                for (int j = 0; j < 2; j++)
                    wmma::mma_sync(sacc[i][j], fa[i], fb[j], sacc[i][j]);
        }
#pragma unroll
        for (int i = 0; i < 2; i++)
#pragma unroll
            for (int j = 0; j < 2; j++)
                wmma::store_matrix_sync(
                    &Ss[(wy * 32 + i * 16) * ALD + wx * 32 + j * 16],
                    sacc[i][j], ALD, wmma::mem_row_major);
        __syncthreads();

        // Online softmax: warp w owns rows [w*16, w*16+16); lane covers 2 cols.
#pragma unroll 4
        for (int rr = 0; rr < 16; rr++) {
            int r = warp * 16 + rr;
            float s0 = Ss[r * ALD + 2 * lane];
            float s1 = Ss[r * ALD + 2 * lane + 1];
            float m = fmaxf(s0, s1);
#pragma unroll
            for (int off = 16; off > 0; off >>= 1)
                m = fmaxf(m, __shfl_xor_sync(0xffffffffu, m, off));
            float old = rmax[r];
            float nm = fmaxf(old, m);
            float alpha = __expf(old - nm);      // 0 on first tile (old=-inf)
            float p0 = __expf(s0 - nm);
            float p1 = __expf(s1 - nm);
            Ss[r * ALD + 2 * lane] = p0;
            Ss[r * ALD + 2 * lane + 1] = p1;
            float ts = p0 + p1;
#pragma unroll
            for (int off = 16; off > 0; off >>= 1)
                ts += __shfl_xor_sync(0xffffffffu, ts, off);
            if (lane == 0) { rsum[r] = rsum[r] * alpha + ts; rmax[r] = nm; }
            Os[r * ALD + 2 * lane] *= alpha;
            Os[r * ALD + 2 * lane + 1] *= alpha;
        }
        __syncthreads();

        // O += P * V   (V = Ks, row-major [key][hd])
        wmma::fragment<wmma::accumulator, 16, 16, 8, float> oacc[2][2];
#pragma unroll
        for (int i = 0; i < 2; i++)
#pragma unroll
            for (int j = 0; j < 2; j++)
                wmma::load_matrix_sync(
                    oacc[i][j],
                    &Os[(wy * 32 + i * 16) * ALD + wx * 32 + j * 16],
                    ALD, wmma::mem_row_major);

#pragma unroll
        for (int kk = 0; kk < 64; kk += 8) {
            wmma::fragment<wmma::matrix_a, 16, 16, 8, wmma::precision::tf32,
                           wmma::row_major> fa[2];
            wmma::fragment<wmma::matrix_b, 16, 16, 8, wmma::precision::tf32,
                           wmma::row_major> fb[2];
#pragma unroll
            for (int i = 0; i < 2; i++) {
                wmma::load_matrix_sync(fa[i], &Ss[(wy * 32 + i * 16) * ALD + kk], ALD);
#pragma unroll
                for (int t = 0; t < fa[i].num_elements; t++)
                    fa[i].x[t] = wmma::__float_to_tf32(fa[i].x[t]);
            }
#pragma unroll
            for (int j = 0; j < 2; j++) {
                wmma::load_matrix_sync(fb[j], &Ks[kk * ALD + wx * 32 + j * 16], ALD);
#pragma unroll
                for (int t = 0; t < fb[j].num_elements; t++)
                    fb[j].x[t] = wmma::__float_to_tf32(fb[j].x[t]);
            }
#pragma unroll
            for (int i = 0; i < 2; i++)
#pragma unroll
                for (int j = 0; j < 2; j++)
                    wmma::mma_sync(oacc[i][j], fa[i], fb[j], oacc[i][j]);
        }
#pragma unroll
        for (int i = 0; i < 2; i++)
#pragma unroll
            for (int j = 0; j < 2; j++)
                wmma::store_matrix_sync(
                    &Os[(wy * 32 + i * 16) * ALD + wx * 32 + j * 16],
                    oacc[i][j], ALD, wmma::mem_row_major);
        __syncthreads();
    }

    // Normalize and write out in [B,N,D] layout.
    float* obase = O + ((b * NN + q0) * DD + h * HD);
#pragma unroll
    for (int l = 0; l < 8; l++) {
        int idx = tid + l * 128;
        int r = idx >> 4;
        int j = (idx & 15) * 4;
        float inv = 1.0f / rsum[r];
        float4 v = *(float4*)&Os[r * ALD + j];
        v.x *= inv; v.y *= inv; v.z *= inv; v.w *= inv;
        *(float4*)&obase[r * DD + j] = v;
    }
}

// ---------------------------------------------------------------------------
// Launch
// ---------------------------------------------------------------------------
extern "C" void kernel_launch(void* const* d_in, const int* in_sizes, int n_in,
                              void* d_out, int out_size)
{
    (void)in_sizes; (void)n_in; (void)out_size;
    const float* x  = (const float*)d_in[0];
    const float* Wq = (const float*)d_in[1];
    const float* bq = (const float*)d_in[2];
    const float* Wk = (const float*)d_in[3];
    const float* bk = (const float*)d_in[4];
    const float* Wp = (const float*)d_in[5];
    const float* bp = (const float*)d_in[6];
    float* out = (float*)d_out;

    float *qbuf, *kbuf, *aobuf;
    cudaGetSymbolAddress((void**)&qbuf, g_Q);
    cudaGetSymbolAddress((void**)&kbuf, g_K);
    cudaGetSymbolAddress((void**)&aobuf, g_AO);

    cudaFuncSetAttribute(attn_kernel,
                         cudaFuncAttributeMaxDynamicSharedMemorySize, ATT_SMEM);

    dim3 ggrid(DD / 64, MTOT / 64);   // (12, 256)
    gemm_bias_kernel<<<ggrid, 128>>>(x, Wq, bq, qbuf, MTOT, DD, DD);
    gemm_bias_kernel<<<ggrid, 128>>>(x, Wk, bk, kbuf, MTOT, DD, DD);

    dim3 agrid(NN / 64, HH, BB);      // (16, 12, 16)
    attn_kernel<<<agrid, 128, ATT_SMEM>>>(qbuf, kbuf, aobuf);

    gemm_bias_kernel<<<ggrid, 128>>>(aobuf, Wp, bp, out, MTOT, DD, DD);
}

// round 3
// speedup vs baseline: 1.7994x; 1.7994x over previous
#include <cuda_runtime.h>
#include <cuda_bf16.h>
#include <mma.h>
#include <cstdint>

using namespace nvcuda;

// Problem constants
#define BB 16
#define NN 1024
#define DD 768
#define HH 12
#define HD 64
#define MTOT (BB * NN)   // 16384
#define SCALE 0.125f     // HD^-0.5

// Scratch (allocation-free rule: __device__ globals)
__device__ float g_Q[MTOT * DD];
__device__ float g_K[MTOT * DD];
__device__ float g_AO[MTOT * DD];

// ---------------------------------------------------------------------------
// cp.async helpers
// ---------------------------------------------------------------------------
__device__ __forceinline__ void cpa16(float* smem_dst, const float* gsrc) {
    uint32_t s = (uint32_t)__cvta_generic_to_shared(smem_dst);
    asm volatile("cp.async.cg.shared.global [%0], [%1], 16;\n" :: "r"(s), "l"(gsrc));
}
#define CP_COMMIT() asm volatile("cp.async.commit_group;\n" ::: "memory")
#define CP_WAIT(n)  asm volatile("cp.async.wait_group %0;\n" :: "n"(n) : "memory")

__device__ __forceinline__ uint32_t f2tf(float x) {
    uint32_t r;
    asm("cvt.rna.tf32.f32 %0, %1;" : "=r"(r) : "f"(x));
    return r;
}

// mma.sync m16n8k8 tf32, A row-major, B col-major, fp32 accumulate (in-place)
__device__ __forceinline__ void mma8(float c[4], const uint32_t a[4],
                                     uint32_t b0, uint32_t b1) {
    asm volatile(
        "mma.sync.aligned.m16n8k8.row.col.f32.tf32.tf32.f32 "
        "{%0,%1,%2,%3}, {%4,%5,%6,%7}, {%8,%9}, {%0,%1,%2,%3};"
        : "+f"(c[0]), "+f"(c[1]), "+f"(c[2]), "+f"(c[3])
        : "r"(a[0]), "r"(a[1]), "r"(a[2]), "r"(a[3]), "r"(b0), "r"(b1));
}

// ---------------------------------------------------------------------------
// GEMM v2: C[m,n] = sum_k A[m,k] * W[n,k] + bias[n]
// Block 128x128, BK=32, 4 warps each computing 64x64 (4x4 wmma tf32 frags).
// cp.async double-buffered staging; bias pre-loaded into accumulators;
// direct fragment->global epilogue.
// ---------------------------------------------------------------------------
#define BK2 32
#define ALD2 40   // 32 + 8 pad
#define GEMM_SMEM ((4 * 128 * ALD2 + 16 * 128) * 4)   // 90112 bytes

__global__ __launch_bounds__(128, 1) void gemm_bias_v2(
    const float* __restrict__ A, const float* __restrict__ W,
    const float* __restrict__ bias, float* __restrict__ C,
    int M, int Nn, int Kk)
{
    extern __shared__ float sm[];
    float* As   = sm;                    // [2][128*ALD2]
    float* Bs   = sm + 2 * 128 * ALD2;   // [2][128*ALD2]
    float* brep = sm + 4 * 128 * ALD2;   // [16][128]

    const int bm = blockIdx.y * 128;
    const int bn = blockIdx.x * 128;
    const int tid = threadIdx.x;
    const int warp = tid >> 5;
    const int wy = warp >> 1;   // 0..1
    const int wx = warp & 1;    // 0..1

    // Replicate bias row (cols bn..bn+127) into 16 identical smem rows.
    for (int idx = tid; idx < 16 * 128; idx += 128)
        brep[idx] = bias[bn + (idx & 127)];
    __syncthreads();

    wmma::fragment<wmma::accumulator, 16, 16, 8, float> acc[4][4];
#pragma unroll
    for (int i = 0; i < 4; i++)
#pragma unroll
        for (int j = 0; j < 4; j++)
            wmma::load_matrix_sync(acc[i][j], &brep[wx * 64 + j * 16], 128,
                                   wmma::mem_row_major);

    // Stage k0=0 into buffer 0.
#pragma unroll
    for (int l = 0; l < 8; l++) {
        int idx = tid + l * 128;
        int r = idx >> 3;
        int c4 = (idx & 7) * 4;
        cpa16(&As[r * ALD2 + c4], &A[(size_t)(bm + r) * Kk + c4]);
        cpa16(&Bs[r * ALD2 + c4], &W[(size_t)(bn + r) * Kk + c4]);
    }
    CP_COMMIT();

    int st = 0;
    for (int k0 = 0; k0 < Kk; k0 += BK2) {
        if (k0 + BK2 < Kk) {
            int nst = st ^ 1;
#pragma unroll
            for (int l = 0; l < 8; l++) {
                int idx = tid + l * 128;
                int r = idx >> 3;
                int c4 = (idx & 7) * 4;
                cpa16(&As[nst * 128 * ALD2 + r * ALD2 + c4],
                      &A[(size_t)(bm + r) * Kk + k0 + BK2 + c4]);
                cpa16(&Bs[nst * 128 * ALD2 + r * ALD2 + c4],
                      &W[(size_t)(bn + r) * Kk + k0 + BK2 + c4]);
            }
            CP_COMMIT();
            CP_WAIT(1);
        } else {
            CP_WAIT(0);
        }
        __syncthreads();

        const float* Ab = &As[st * 128 * ALD2 + wy * 64 * ALD2];
        const float* Bb = &Bs[st * 128 * ALD2 + wx * 64 * ALD2];

#pragma unroll
        for (int kk = 0; kk < BK2; kk += 8) {
            wmma::fragment<wmma::matrix_a, 16, 16, 8, wmma::precision::tf32,
                           wmma::row_major> fa[4];
            wmma::fragment<wmma::matrix_b, 16, 16, 8, wmma::precision::tf32,
                           wmma::col_major> fb[4];
#pragma unroll
            for (int i = 0; i < 4; i++) {
                wmma::load_matrix_sync(fa[i], Ab + i * 16 * ALD2 + kk, ALD2);
#pragma unroll
                for (int t = 0; t < fa[i].num_elements; t++)
                    fa[i].x[t] = wmma::__float_to_tf32(fa[i].x[t]);
            }
#pragma unroll
            for (int j = 0; j < 4; j++) {
                wmma::load_matrix_sync(fb[j], Bb + j * 16 * ALD2 + kk, ALD2);
#pragma unroll
                for (int t = 0; t < fb[j].num_elements; t++)
                    fb[j].x[t] = wmma::__float_to_tf32(fb[j].x[t]);
            }
#pragma unroll
            for (int i = 0; i < 4; i++)
#pragma unroll
                for (int j = 0; j < 4; j++)
                    wmma::mma_sync(acc[i][j], fa[i], fb[j], acc[i][j]);
        }
        st ^= 1;
        __syncthreads();
    }

    // Direct epilogue: fragments -> global (bias already inside).
#pragma unroll
    for (int i = 0; i < 4; i++)
#pragma unroll
        for (int j = 0; j < 4; j++)
            wmma::store_matrix_sync(
                &C[(size_t)(bm + wy * 64 + i * 16) * Nn + bn + wx * 64 + j * 16],
                acc[i][j], Nn, wmma::mem_row_major);
}

// ---------------------------------------------------------------------------
// Attention v2 (FlashAttention-2 style), V = K.
// Block = (b, h, 64-query tile); 4 warps; each warp owns 16 query rows.
// Q fragments + O accumulators + softmax state in registers.
// K tiles double-buffered via cp.async. P repacked via per-warp smem tile.
// mma.sync m16n8k8 tf32 with documented fragment layouts:
//   A(16x8): a0(r=g,c=t) a1(r=g+8,c=t) a2(r=g,c=t+4) a3(r=g+8,c=t+4)
//   B(8x8) col: b0(row=t,col=g) b1(row=t+4,col=g)
//   C(16x8): c0(r=g,c=2t) c1(r=g,c=2t+1) c2(r=g+8,c=2t) c3(r=g+8,c=2t+1)
//   where g = lane>>2, t = lane&3.
// ---------------------------------------------------------------------------
#define KLD 68
#define PLD 68
#define ATT_SMEM ((2 * 64 * KLD + 4 * 16 * PLD) * 4)   // 52224 bytes

__global__ __launch_bounds__(128, 1) void attn_v2(
    const float* __restrict__ Q, const float* __restrict__ K,
    float* __restrict__ O)
{
    extern __shared__ float sm[];
    float* Ks = sm;                   // [2][64*KLD]
    float* Pw = sm + 2 * 64 * KLD + (threadIdx.x >> 5) * 16 * PLD;

    const int b  = blockIdx.z;
    const int h  = blockIdx.y;
    const int q0 = blockIdx.x * 64;
    const int tid = threadIdx.x;
    const int warp = tid >> 5;
    const int lane = tid & 31;
    const int g  = lane >> 2;
    const int t4 = lane & 3;

    // Q fragments (8 k-steps over HD=64), pre-scaled by SCALE, tf32.
    uint32_t aq[8][4];
    {
        const float* qb = Q + (size_t)(b * NN + q0 + warp * 16) * DD + h * HD;
#pragma unroll
        for (int ks = 0; ks < 8; ks++) {
            aq[ks][0] = f2tf(qb[g * DD + ks * 8 + t4] * SCALE);
            aq[ks][1] = f2tf(qb[(g + 8) * DD + ks * 8 + t4] * SCALE);
            aq[ks][2] = f2tf(qb[g * DD + ks * 8 + t4 + 4] * SCALE);
            aq[ks][3] = f2tf(qb[(g + 8) * DD + ks * 8 + t4 + 4] * SCALE);
        }
    }

    float Oc[8][4];
#pragma unroll
    for (int n = 0; n < 8; n++)
#pragma unroll
        for (int e = 0; e < 4; e++) Oc[n][e] = 0.0f;
    float mrow[2] = {-INFINITY, -INFINITY};
    float lrow[2] = {0.0f, 0.0f};

    // Stage K tile 0.
#pragma unroll
    for (int l = 0; l < 8; l++) {
        int idx = tid + l * 128;
        int r = idx >> 4;
        int c4 = (idx & 15) * 4;
        cpa16(&Ks[r * KLD + c4],
              &K[(size_t)(b * NN + r) * DD + h * HD + c4]);
    }
    CP_COMMIT();

    int st = 0;
    for (int kt = 0; kt < NN / 64; kt++) {
        if (kt + 1 < NN / 64) {
            int nst = st ^ 1;
#pragma unroll
            for (int l = 0; l < 8; l++) {
                int idx = tid + l * 128;
                int r = idx >> 4;
                int c4 = (idx & 15) * 4;
                cpa16(&Ks[nst * 64 * KLD + r * KLD + c4],
                      &K[(size_t)(b * NN + (kt + 1) * 64 + r) * DD + h * HD + c4]);
            }
            CP_COMMIT();
            CP_WAIT(1);
        } else {
            CP_WAIT(0);
        }
        __syncthreads();

        const float* Kt = &Ks[st * 64 * KLD];

        // ---- S = Q * K^T  (16 x 64 per warp) ----
        float sc[8][4];
#pragma unroll
        for (int n = 0; n < 8; n++)
#pragma unroll
            for (int e = 0; e < 4; e++) sc[n][e] = 0.0f;

#pragma unroll
        for (int n = 0; n < 8; n++) {
#pragma unroll
            for (int ks = 0; ks < 8; ks++) {
                // B[d][key]: b0 = K[key0+g][d0+t4], b1 = K[key0+g][d0+t4+4]
                uint32_t b0 = f2tf(Kt[(n * 8 + g) * KLD + ks * 8 + t4]);
                uint32_t b1 = f2tf(Kt[(n * 8 + g) * KLD + ks * 8 + t4 + 4]);
                mma8(sc[n], aq[ks], b0, b1);
            }
        }

        // ---- register online softmax, per row-half ----
#pragma unroll
        for (int hh = 0; hh < 2; hh++) {
            float mx = -INFINITY;
#pragma unroll
            for (int n = 0; n < 8; n++)
                mx = fmaxf(mx, fmaxf(sc[n][2 * hh], sc[n][2 * hh + 1]));
            mx = fmaxf(mx, __shfl_xor_sync(0xffffffffu, mx, 1));
            mx = fmaxf(mx, __shfl_xor_sync(0xffffffffu, mx, 2));
            float mnew = fmaxf(mrow[hh], mx);
            float alpha = __expf(mrow[hh] - mnew);   // 0 on first tile
            mrow[hh] = mnew;
            float ps = 0.0f;
#pragma unroll
            for (int n = 0; n < 8; n++) {
                float p0 = __expf(sc[n][2 * hh] - mnew);
                float p1 = __expf(sc[n][2 * hh + 1] - mnew);
                sc[n][2 * hh] = p0;
                sc[n][2 * hh + 1] = p1;
                ps += p0 + p1;
            }
            ps += __shfl_xor_sync(0xffffffffu, ps, 1);
            ps += __shfl_xor_sync(0xffffffffu, ps, 2);
            lrow[hh] = lrow[hh] * alpha + ps;
#pragma unroll
            for (int n = 0; n < 8; n++) {
                Oc[n][2 * hh] *= alpha;
                Oc[n][2 * hh + 1] *= alpha;
            }
        }

        // ---- P -> per-warp smem (C-layout to A-layout repack) ----
#pragma unroll
        for (int n = 0; n < 8; n++) {
            *(float2*)&Pw[g * PLD + n * 8 + 2 * t4] =
                make_float2(sc[n][0], sc[n][1]);
            *(float2*)&Pw[(g + 8) * PLD + n * 8 + 2 * t4] =
                make_float2(sc[n][2], sc[n][3]);
        }
        __syncwarp();

        // ---- O += P * V   (V = Kt) ----
#pragma unroll
        for (int ks = 0; ks < 8; ks++) {
            uint32_t pa[4];
            pa[0] = f2tf(Pw[g * PLD + ks * 8 + t4]);
            pa[1] = f2tf(Pw[(g + 8) * PLD + ks * 8 + t4]);
            pa[2] = f2tf(Pw[g * PLD + ks * 8 + t4 + 4]);
            pa[3] = f2tf(Pw[(g + 8) * PLD + ks * 8 + t4 + 4]);
#pragma unroll
            for (int n = 0; n < 8; n++) {
                // B[key][d]: b0 = V[key0+t4][d0+g], b1 = V[key0+t4+4][d0+g]
                uint32_t b0 = f2tf(Kt[(ks * 8 + t4) * KLD + n * 8 + g]);
                uint32_t b1 = f2tf(Kt[(ks * 8 + t4 + 4) * KLD + n * 8 + g]);
                mma8(Oc[n], pa, b0, b1);
            }
        }

        st ^= 1;
        __syncthreads();
    }

    // Normalize and store O (row-major [B,N,D]).
    float inv0 = 1.0f / lrow[0];
    float inv1 = 1.0f / lrow[1];
    float* ob = O + (size_t)(b * NN + q0 + warp * 16) * DD + h * HD;
#pragma unroll
    for (int n = 0; n < 8; n++) {
        *(float2*)&ob[g * DD + n * 8 + 2 * t4] =
            make_float2(Oc[n][0] * inv0, Oc[n][1] * inv0);
        *(float2*)&ob[(g + 8) * DD + n * 8 + 2 * t4] =
            make_float2(Oc[n][2] * inv1, Oc[n][3] * inv1);
    }
}

// ---------------------------------------------------------------------------
// Launch
// ---------------------------------------------------------------------------
extern "C" void kernel_launch(void* const* d_in, const int* in_sizes, int n_in,
                              void* d_out, int out_size)
{
    (void)in_sizes; (void)n_in; (void)out_size;
    const float* x  = (const float*)d_in[0];
    const float* Wq = (const float*)d_in[1];
    const float* bq = (const float*)d_in[2];
    const float* Wk = (const float*)d_in[3];
    const float* bk = (const float*)d_in[4];
    const float* Wp = (const float*)d_in[5];
    const float* bp = (const float*)d_in[6];
    float* out = (float*)d_out;

    float *qbuf, *kbuf, *aobuf;
    cudaGetSymbolAddress((void**)&qbuf, g_Q);
    cudaGetSymbolAddress((void**)&kbuf, g_K);
    cudaGetSymbolAddress((void**)&aobuf, g_AO);

    cudaFuncSetAttribute(gemm_bias_v2,
                         cudaFuncAttributeMaxDynamicSharedMemorySize, GEMM_SMEM);
    cudaFuncSetAttribute(attn_v2,
                         cudaFuncAttributeMaxDynamicSharedMemorySize, ATT_SMEM);

    dim3 ggrid(DD / 128, MTOT / 128);   // (6, 128)
    gemm_bias_v2<<<ggrid, 128, GEMM_SMEM>>>(x, Wq, bq, qbuf, MTOT, DD, DD);
    gemm_bias_v2<<<ggrid, 128, GEMM_SMEM>>>(x, Wk, bk, kbuf, MTOT, DD, DD);

    dim3 agrid(NN / 64, HH, BB);        // (16, 12, 16)
    attn_v2<<<agrid, 128, ATT_SMEM>>>(qbuf, kbuf, aobuf);

    gemm_bias_v2<<<ggrid, 128, GEMM_SMEM>>>(aobuf, Wp, bp, out, MTOT, DD, DD);
}